// round 3
// baseline (speedup 1.0000x reference)
#include <cuda_runtime.h>

// Problem-fixed dimensions
#define NNODES 65536            // B*n
#define HID    128
#define NHEAD  4
#define CDIM   32
#define NEDGE  262144           // 2*B*EH (bidirectional)
#define NTOT   (NEDGE + NNODES) // + self loops
#define NB     64
#define NPG    1024
#define NA     32
#define ADIM   7
#define NIDX   4
#define NLAY   3
#define NEG    0.2f

// Scratch (static device allocations only — harness forbids cudaMalloc)
__device__ float g_h [NNODES * HID];
__device__ float g_xl[NNODES * HID];
__device__ float g_xr[NNODES * HID];
__device__ int   g_deg[NNODES];
__device__ int   g_cur[NNODES];
__device__ int   g_ptr[NNODES + 1];
__device__ int   g_adj[NTOT];
__device__ float g_easum;
__device__ float g_tree[NB * 3 * HID];

// ---------------------------------------------------------------------------
__global__ void k_init() {
    int i = blockIdx.x * blockDim.x + threadIdx.x;
    if (i < NNODES) { g_deg[i] = 1; g_cur[i] = 0; }   // deg starts at 1 (self loop)
    if (i == 0) g_easum = 0.f;
}

__global__ void k_easum(const float* __restrict__ ea) {
    int i = blockIdx.x * 256 + threadIdx.x;   // grid covers NEDGE exactly
    float v = ea[i];
    #pragma unroll
    for (int o = 16; o; o >>= 1) v += __shfl_xor_sync(0xffffffffu, v, o);
    __shared__ float ws[8];
    if ((threadIdx.x & 31) == 0) ws[threadIdx.x >> 5] = v;
    __syncthreads();
    if (threadIdx.x == 0) {
        float s = 0.f;
        #pragma unroll
        for (int w = 0; w < 8; w++) s += ws[w];
        atomicAdd(&g_easum, s);
    }
}

__global__ void k_deg(const int* __restrict__ edst) {
    int e = blockIdx.x * 256 + threadIdx.x;   // grid covers NEDGE exactly
    atomicAdd(&g_deg[edst[e]], 1);
}

// Single-block exclusive scan over 65536 degrees (64 chunks of 1024)
__global__ void k_scan() {
    __shared__ int sh[1024];
    int t = threadIdx.x;
    int carry = 0;
    for (int base = 0; base < NNODES; base += 1024) {
        int v = g_deg[base + t];
        sh[t] = v;
        __syncthreads();
        for (int off = 1; off < 1024; off <<= 1) {
            int add = (t >= off) ? sh[t - off] : 0;
            __syncthreads();
            sh[t] += add;
            __syncthreads();
        }
        g_ptr[base + t] = carry + sh[t] - v;   // exclusive
        int tot = sh[1023];
        __syncthreads();
        carry += tot;
    }
    if (t == 0) g_ptr[NNODES] = carry;
}

__global__ void k_scatter(const int* __restrict__ edst) {
    int i = blockIdx.x * 256 + threadIdx.x;
    if (i >= NTOT) return;
    if (i < NEDGE) {
        int d = edst[i];
        int p = atomicAdd(&g_cur[d], 1);
        g_adj[g_ptr[d] + p] = i;
    } else {
        int nd = i - NEDGE;
        int p = atomicAdd(&g_cur[nd], 1);
        g_adj[g_ptr[nd] + p] = NEDGE + nd;     // id >= NEDGE encodes self loop
    }
}

// h = relu(x * Wn + bn) ;  x is [N,1]
__global__ void k_h0(const float* __restrict__ x, const float* __restrict__ Wn,
                     const float* __restrict__ bn) {
    int i = blockIdx.x * 256 + threadIdx.x;   // grid covers N*HID
    int node = i >> 7, j = i & 127;
    g_h[i] = fmaxf(fmaf(x[node], Wn[j], bn[j]), 0.f);
}

// Fused xl = h@Wl + bl, xr = h@Wr + br.  16 rows per block, 256 threads:
// threads [0,128) -> Wl/xl, [128,256) -> Wr/xr, each thread one output column.
#define GR 16
__global__ void __launch_bounds__(256, 6)
k_gemm2(const float* __restrict__ Wl, const float* __restrict__ bl,
        const float* __restrict__ Wr, const float* __restrict__ br) {
    __shared__ __align__(16) float hs[GR][HID];
    int row0 = blockIdx.x * GR;
    int t = threadIdx.x;
    for (int i = t; i < GR * HID; i += 256)
        hs[i >> 7][i & 127] = g_h[row0 * HID + i];
    __syncthreads();

    int j = t & 127;
    const float* W  = (t < 128) ? Wl : Wr;
    float bv        = (t < 128) ? bl[j] : br[j];
    float* out      = (t < 128) ? g_xl : g_xr;

    float acc[GR];
    #pragma unroll
    for (int r = 0; r < GR; r++) acc[r] = bv;

    #pragma unroll 4
    for (int k = 0; k < HID; k += 4) {
        float w0 = W[(k + 0) * HID + j];
        float w1 = W[(k + 1) * HID + j];
        float w2 = W[(k + 2) * HID + j];
        float w3 = W[(k + 3) * HID + j];
        #pragma unroll
        for (int r = 0; r < GR; r++) {
            float4 hv = *(const float4*)&hs[r][k];
            acc[r] = fmaf(hv.x, w0, fmaf(hv.y, w1, fmaf(hv.z, w2, fmaf(hv.w, w3, acc[r]))));
        }
    }
    #pragma unroll
    for (int r = 0; r < GR; r++)
        out[(row0 + r) * HID + j] = acc[r];
}

// GATv2 edge pass: one block per dst node, 128 threads (warp == head).
// Online softmax over incident edges, then weighted aggregate + residual relu.
__global__ void k_gat(const int* __restrict__ esrc, const float* __restrict__ ea,
                      const float* __restrict__ We, const float* __restrict__ att,
                      const float* __restrict__ gb) {
    int node = blockIdx.x;
    int t = threadIdx.x;
    int c = t & 31, hd = t >> 5;

    float xrv = g_xr[node * HID + t];
    float wev = We[t];
    float av  = att[hd * CDIM + c];
    float eam = g_easum * (1.0f / NEDGE);

    int kb = g_ptr[node], ke = g_ptr[node + 1];

    float m = -1e30f, s = 0.f;
    for (int k = kb; k < ke; k++) {
        int eid = g_adj[k];
        int sn; float eav;
        if (eid < NEDGE) { sn = esrc[eid]; eav = ea[eid]; }
        else             { sn = node;      eav = eam;     }
        float v = g_xl[sn * HID + t] + xrv + eav * wev;
        v = (v > 0.f) ? v : NEG * v;
        float p = v * av;
        #pragma unroll
        for (int o = 16; o; o >>= 1) p += __shfl_xor_sync(0xffffffffu, p, o);
        float mn = fmaxf(m, p);
        s = s * __expf(m - mn) + __expf(p - mn);
        m = mn;
    }
    float inv = 1.0f / s;

    float acc = 0.f;
    for (int k = kb; k < ke; k++) {
        int eid = g_adj[k];
        int sn; float eav;
        if (eid < NEDGE) { sn = esrc[eid]; eav = ea[eid]; }
        else             { sn = node;      eav = eam;     }
        float xlv = g_xl[sn * HID + t];
        float v = xlv + xrv + eav * wev;
        v = (v > 0.f) ? v : NEG * v;
        float p = v * av;
        #pragma unroll
        for (int o = 16; o; o >>= 1) p += __shfl_xor_sync(0xffffffffu, p, o);
        acc += __expf(p - m) * inv * xlv;
    }
    float o = acc + gb[t];
    g_h[node * HID + t] += (o > 0.f) ? o : 0.f;
}

// sum / mean / max pooling per graph -> g_tree[b][384]
__global__ void k_pool() {
    int b = blockIdx.x, t = threadIdx.x;
    const float* hp = g_h + (size_t)(b * NPG) * HID + t;
    float s = 0.f, mx = -1e30f;
    for (int i = 0; i < NPG; i++) {
        float v = hp[(size_t)i * HID];
        s += v; mx = fmaxf(mx, v);
    }
    g_tree[b * 3 * HID + t]            = s;
    g_tree[b * 3 * HID + HID + t]      = s * (1.0f / NPG);
    g_tree[b * 3 * HID + 2 * HID + t]  = mx;
}

// Fused action-MLP + Q-MLP: one block per (graph, action), 128 threads.
__global__ void k_act(const float* __restrict__ act, const int* __restrict__ bptr,
                      const float* __restrict__ aW1, const float* __restrict__ ab1,
                      const float* __restrict__ aW2, const float* __restrict__ ab2,
                      const float* __restrict__ qW1, const float* __restrict__ qb1,
                      const float* __restrict__ qW2, const float* __restrict__ qb2,
                      const float* __restrict__ qW3, const float* __restrict__ qb3,
                      float* __restrict__ out) {
    const int AI = NIDX * HID + (ADIM - NIDX);   // 515
    int b = blockIdx.x / NA, a = blockIdx.x % NA;
    int t = threadIdx.x;

    __shared__ float ai[NIDX * HID + (ADIM - NIDX)];
    __shared__ float v1[HID];
    __shared__ float v2[HID];

    const float* arow = act + (size_t)(b * NA + a) * ADIM;
    int base = bptr[b];
    #pragma unroll
    for (int i = 0; i < NIDX; i++) {
        int nidx = (int)arow[i] + base;
        ai[i * HID + t] = g_h[(size_t)nidx * HID + t];
    }
    if (t < ADIM - NIDX) ai[NIDX * HID + t] = arow[NIDX + t];
    __syncthreads();

    float s = ab1[t];
    for (int k = 0; k < AI; k++) s = fmaf(ai[k], aW1[k * HID + t], s);
    v1[t] = fmaxf(s, 0.f);
    __syncthreads();

    s = ab2[t];
    #pragma unroll 4
    for (int k = 0; k < HID; k++) s = fmaf(v1[k], aW2[k * HID + t], s);
    v2[t] = fmaxf(s, 0.f);                        // ae
    __syncthreads();

    const float* tr = g_tree + b * 3 * HID;
    s = qb1[t];
    #pragma unroll 4
    for (int k = 0; k < 3 * HID; k++) s = fmaf(tr[k], qW1[k * HID + t], s);
    #pragma unroll 4
    for (int k = 0; k < HID; k++)     s = fmaf(v2[k], qW1[(3 * HID + k) * HID + t], s);
    v1[t] = fmaxf(s, 0.f);
    __syncthreads();

    s = qb2[t];
    #pragma unroll 4
    for (int k = 0; k < HID; k++) s = fmaf(v1[k], qW2[k * HID + t], s);
    float q = fmaxf(s, 0.f) * qW3[t];
    #pragma unroll
    for (int o = 16; o; o >>= 1) q += __shfl_xor_sync(0xffffffffu, q, o);
    __shared__ float ws[4];
    if ((t & 31) == 0) ws[t >> 5] = q;
    __syncthreads();
    if (t == 0) out[b * NA + a] = ws[0] + ws[1] + ws[2] + ws[3] + qb3[0];
}

// ---------------------------------------------------------------------------
extern "C" void kernel_launch(void* const* d_in, const int* in_sizes, int n_in,
                              void* d_out, int out_size) {
    const float *x, *edge_attr, *act, *Wn, *bn, *gWl, *gbl, *gWr, *gbr, *gWe, *gatt, *gb;
    const float *aW1, *ab1, *aW2, *ab2, *qW1, *qb1, *qW2, *qb2, *qW3, *qb3;
    const int *eidx, *bptr;

    if (in_sizes[3] == 2 * NEDGE) {
        // dict order: x, edge_attr, action_tensor, edge_index, batch_idx, batch_ptr,
        //             Wn, bn, gWl, gWr, gWe, gatt, gbl, gbr, gb, aW1..qb3
        x = (const float*)d_in[0];  edge_attr = (const float*)d_in[1];
        act = (const float*)d_in[2];
        eidx = (const int*)d_in[3]; bptr = (const int*)d_in[5];
        Wn = (const float*)d_in[6];  bn  = (const float*)d_in[7];
        gWl = (const float*)d_in[8]; gWr = (const float*)d_in[9];
        gWe = (const float*)d_in[10]; gatt = (const float*)d_in[11];
        gbl = (const float*)d_in[12]; gbr = (const float*)d_in[13];
        gb  = (const float*)d_in[14];
        aW1 = (const float*)d_in[15]; ab1 = (const float*)d_in[16];
        aW2 = (const float*)d_in[17]; ab2 = (const float*)d_in[18];
        qW1 = (const float*)d_in[19]; qb1 = (const float*)d_in[20];
        qW2 = (const float*)d_in[21]; qb2 = (const float*)d_in[22];
        qW3 = (const float*)d_in[23]; qb3 = (const float*)d_in[24];
    } else {
        // reference-signature order
        x = (const float*)d_in[0];  edge_attr = (const float*)d_in[1];
        act = (const float*)d_in[2];
        Wn = (const float*)d_in[3];  bn  = (const float*)d_in[4];
        gWl = (const float*)d_in[5]; gbl = (const float*)d_in[6];
        gWr = (const float*)d_in[7]; gbr = (const float*)d_in[8];
        gWe = (const float*)d_in[9]; gatt = (const float*)d_in[10];
        gb  = (const float*)d_in[11];
        aW1 = (const float*)d_in[12]; ab1 = (const float*)d_in[13];
        aW2 = (const float*)d_in[14]; ab2 = (const float*)d_in[15];
        qW1 = (const float*)d_in[16]; qb1 = (const float*)d_in[17];
        qW2 = (const float*)d_in[18]; qb2 = (const float*)d_in[19];
        qW3 = (const float*)d_in[20]; qb3 = (const float*)d_in[21];
        eidx = (const int*)d_in[22]; bptr = (const int*)d_in[24];
    }
    float* out = (float*)d_out;
    const int* esrc = eidx;
    const int* edst = eidx + NEDGE;

    // Graph structure (rebuilt every launch: deterministic, input-dependent)
    k_init   <<<NNODES / 256, 256>>>();
    k_easum  <<<NEDGE / 256, 256>>>(edge_attr);
    k_deg    <<<NEDGE / 256, 256>>>(edst);
    k_scan   <<<1, 1024>>>();
    k_scatter<<<(NTOT + 255) / 256, 256>>>(edst);

    // Node encoder
    k_h0<<<(NNODES * HID) / 256, 256>>>(x, Wn, bn);

    // GATv2 layers
    for (int l = 0; l < NLAY; l++) {
        k_gemm2<<<NNODES / GR, 256>>>(gWl + l * HID * HID, gbl + l * HID,
                                      gWr + l * HID * HID, gbr + l * HID);
        k_gat<<<NNODES, 128>>>(esrc, edge_attr,
                               gWe + l * HID, gatt + l * NHEAD * CDIM, gb + l * HID);
    }

    // Readout + heads
    k_pool<<<NB, HID>>>();
    k_act<<<NB * NA, HID>>>(act, bptr, aW1, ab1, aW2, ab2,
                            qW1, qb1, qW2, qb2, qW3, qb3, out);
}

// round 5
// speedup vs baseline: 1.3722x; 1.3722x over previous
#include <cuda_runtime.h>

// Problem-fixed dimensions
#define NNODES 65536            // B*n
#define HID    128
#define NHEAD  4
#define CDIM   32
#define NEDGE  262144           // 2*B*EH (bidirectional)
#define NTOT   (NEDGE + NNODES) // + self loops
#define NB     64
#define NPG    1024
#define NA     32
#define ADIM   7
#define NIDX   4
#define NLAY   3
#define NEG    0.2f

typedef unsigned long long u64;

// Scratch (static device allocations only — harness forbids cudaMalloc)
__device__ float g_h [NNODES * HID];
__device__ float g_xl[NNODES * HID];
__device__ float g_xr[NNODES * HID];
__device__ int   g_deg[NNODES];
__device__ int   g_cur[NNODES];
__device__ int   g_ptr[NNODES + 1];
__device__ int   g_bsum[256];
__device__ int   g_adj[NTOT];
__device__ float g_easum;
__device__ float g_tree[NB * 3 * HID];
__device__ float g_q1b [NB * HID];

// ---- f32x2 helpers (FFMA2: 2x fp32 FMA throughput, PTX-only on sm_103a) ----
__device__ __forceinline__ void fma2(u64& d, u64 a, u64 b) {
    asm("fma.rn.f32x2 %0, %1, %2, %0;" : "+l"(d) : "l"(a), "l"(b));
}
__device__ __forceinline__ u64 pack2(float lo, float hi) {
    u64 r; asm("mov.b64 %0, {%1, %2};" : "=l"(r) : "f"(lo), "f"(hi)); return r;
}
__device__ __forceinline__ void unpack2(float& lo, float& hi, u64 v) {
    asm("mov.b64 {%0, %1}, %2;" : "=f"(lo), "=f"(hi) : "l"(v));
}

// ---------------------------------------------------------------------------
__global__ void k_init() {
    int i = blockIdx.x * blockDim.x + threadIdx.x;
    if (i < NNODES) { g_deg[i] = 1; g_cur[i] = 0; }   // deg starts at 1 (self loop)
    if (i == 0) g_easum = 0.f;
}

__global__ void k_easum(const float* __restrict__ ea) {
    int i = blockIdx.x * 256 + threadIdx.x;   // grid covers NEDGE exactly
    float v = ea[i];
    #pragma unroll
    for (int o = 16; o; o >>= 1) v += __shfl_xor_sync(0xffffffffu, v, o);
    __shared__ float ws[8];
    if ((threadIdx.x & 31) == 0) ws[threadIdx.x >> 5] = v;
    __syncthreads();
    if (threadIdx.x == 0) {
        float s = 0.f;
        #pragma unroll
        for (int w = 0; w < 8; w++) s += ws[w];
        atomicAdd(&g_easum, s);
    }
}

__global__ void k_deg(const int* __restrict__ edst) {
    int e = blockIdx.x * 256 + threadIdx.x;   // grid covers NEDGE exactly
    atomicAdd(&g_deg[edst[e]], 1);
}

// Hierarchical exclusive scan: 256 blocks x 256 + 1x256 + 256x256
__global__ void k_scan1() {
    __shared__ int sh[256];
    int b = blockIdx.x, t = threadIdx.x;
    int v = g_deg[b * 256 + t];
    sh[t] = v;
    __syncthreads();
    for (int off = 1; off < 256; off <<= 1) {
        int add = (t >= off) ? sh[t - off] : 0;
        __syncthreads();
        sh[t] += add;
        __syncthreads();
    }
    g_ptr[b * 256 + t] = sh[t] - v;          // exclusive within block
    if (t == 255) g_bsum[b] = sh[255];
}

__global__ void k_scan2() {
    __shared__ int sh[256];
    int t = threadIdx.x;
    int v = g_bsum[t];
    sh[t] = v;
    __syncthreads();
    for (int off = 1; off < 256; off <<= 1) {
        int add = (t >= off) ? sh[t - off] : 0;
        __syncthreads();
        sh[t] += add;
        __syncthreads();
    }
    g_bsum[t] = sh[t] - v;                   // exclusive block offsets
}

__global__ void k_scan3() {
    int b = blockIdx.x, t = threadIdx.x;
    g_ptr[b * 256 + t] += g_bsum[b];
    if (b == 0 && t == 0) g_ptr[NNODES] = NTOT;   // total is statically known
}

__global__ void k_scatter(const int* __restrict__ edst) {
    int i = blockIdx.x * 256 + threadIdx.x;
    if (i >= NTOT) return;
    if (i < NEDGE) {
        int d = edst[i];
        int p = atomicAdd(&g_cur[d], 1);
        g_adj[g_ptr[d] + p] = i;
    } else {
        int nd = i - NEDGE;
        int p = atomicAdd(&g_cur[nd], 1);
        g_adj[g_ptr[nd] + p] = NEDGE + nd;     // id >= NEDGE encodes self loop
    }
}

// h = relu(x * Wn + bn) ;  x is [N,1]
__global__ void k_h0(const float* __restrict__ x, const float* __restrict__ Wn,
                     const float* __restrict__ bn) {
    int i = blockIdx.x * 256 + threadIdx.x;   // grid covers N*HID
    int node = i >> 7, j = i & 127;
    g_h[i] = fmaxf(fmaf(x[node], Wn[j], bn[j]), 0.f);
}

// Fused xl = h@Wl + bl, xr = h@Wr + br using FFMA2 (fma.rn.f32x2).
// 32 rows per block, 256 threads. Shared holds h TRANSPOSED (hst[k][r]) so
// row pairs are contiguous -> f32x2 lanes = (row r, row r+1), w duplicated.
// Thread layout: half = t>>7 picks rows [0,16) or [16,32);
//                tt = t&127: tt<64 -> Wl cols 2*tt(+1), else Wr.
#define GR 32
__global__ void __launch_bounds__(256, 2)
k_gemm2(const float* __restrict__ Wl, const float* __restrict__ bl,
        const float* __restrict__ Wr, const float* __restrict__ br) {
    __shared__ __align__(16) float hst[HID][GR + 4];   // pad 4 keeps 16B align
    int row0 = blockIdx.x * GR;
    int t = threadIdx.x;

    for (int i = t; i < GR * HID; i += 256) {
        int r = i >> 7, k = i & 127;
        hst[k][r] = g_h[row0 * HID + i];
    }
    __syncthreads();

    int half = t >> 7;                 // row group: 0 -> rows 0..15, 1 -> 16..31
    int tt = t & 127;
    const float* W  = (tt < 64) ? Wl : Wr;
    const float* bb = (tt < 64) ? bl : br;
    float* out      = (tt < 64) ? g_xl : g_xr;
    int j0 = (tt & 63) * 2;
    int r0 = half * 16;

    // acc[p*2+c] = f32x2 over rows (r0+2p, r0+2p+1), column j0+c
    u64 acc[16];
    #pragma unroll
    for (int p = 0; p < 8; p++) {
        acc[p * 2 + 0] = pack2(bb[j0 + 0], bb[j0 + 0]);
        acc[p * 2 + 1] = pack2(bb[j0 + 1], bb[j0 + 1]);
    }

    #pragma unroll 8
    for (int k = 0; k < HID; k++) {
        float2 wv = *(const float2*)&W[k * HID + j0];
        u64 w0 = pack2(wv.x, wv.x);
        u64 w1 = pack2(wv.y, wv.y);
        const ulonglong2* hp = (const ulonglong2*)&hst[k][r0];
        #pragma unroll
        for (int m = 0; m < 4; m++) {
            ulonglong2 h2 = hp[m];     // rows r0+4m .. r0+4m+3 as two f32x2
            fma2(acc[(2 * m + 0) * 2 + 0], h2.x, w0);
            fma2(acc[(2 * m + 0) * 2 + 1], h2.x, w1);
            fma2(acc[(2 * m + 1) * 2 + 0], h2.y, w0);
            fma2(acc[(2 * m + 1) * 2 + 1], h2.y, w1);
        }
    }

    #pragma unroll
    for (int p = 0; p < 8; p++) {
        float l0, h0v, l1, h1v;
        unpack2(l0, h0v, acc[p * 2 + 0]);
        unpack2(l1, h1v, acc[p * 2 + 1]);
        int row = row0 + r0 + 2 * p;
        *(float2*)&out[(size_t)row * HID + j0]       = make_float2(l0, l1);
        *(float2*)&out[(size_t)(row + 1) * HID + j0] = make_float2(h0v, h1v);
    }
}

// GATv2 edge pass, SINGLE-PASS online softmax (acc rescaled with s).
// One block per dst node, 128 threads (warp == head).
__global__ void k_gat(const int* __restrict__ esrc, const float* __restrict__ ea,
                      const float* __restrict__ We, const float* __restrict__ att,
                      const float* __restrict__ gb) {
    int node = blockIdx.x;
    int t = threadIdx.x;
    int c = t & 31, hd = t >> 5;

    float xrv = g_xr[node * HID + t];
    float wev = We[t];
    float av  = att[hd * CDIM + c];
    float eam = g_easum * (1.0f / NEDGE);

    int kb = g_ptr[node], ke = g_ptr[node + 1];

    float m = -1e30f, s = 0.f, acc = 0.f;
    for (int k = kb; k < ke; k++) {
        int eid = g_adj[k];
        int sn; float eav;
        if (eid < NEDGE) { sn = esrc[eid]; eav = ea[eid]; }
        else             { sn = node;      eav = eam;     }
        float xlv = g_xl[sn * HID + t];
        float v = xlv + xrv + eav * wev;
        v = (v > 0.f) ? v : NEG * v;
        float p = v * av;
        #pragma unroll
        for (int o = 16; o; o >>= 1) p += __shfl_xor_sync(0xffffffffu, p, o);
        float mn = fmaxf(m, p);
        float sc = __expf(m - mn);
        float w  = __expf(p - mn);
        s   = s * sc + w;
        acc = acc * sc + w * xlv;
        m = mn;
    }
    float o = acc / s + gb[t];
    g_h[node * HID + t] += (o > 0.f) ? o : 0.f;
}

// sum/mean/max pooling per graph, 1024 threads (8 row groups x 128 channels)
__global__ void k_pool() {
    int b = blockIdx.x, t = threadIdx.x;
    int c = t & 127, g = t >> 7;
    float s = 0.f, mx = -1e30f;
    for (int i = g; i < NPG; i += 8) {
        float v = g_h[((size_t)(b * NPG + i)) * HID + c];
        s += v; mx = fmaxf(mx, v);
    }
    __shared__ float ss[8][128], sm[8][128];
    ss[g][c] = s; sm[g][c] = mx;
    __syncthreads();
    if (g == 0) {
        #pragma unroll
        for (int j = 1; j < 8; j++) { s += ss[j][c]; mx = fmaxf(mx, sm[j][c]); }
        g_tree[b * 3 * HID + c]           = s;
        g_tree[b * 3 * HID + HID + c]     = s * (1.0f / NPG);
        g_tree[b * 3 * HID + 2 * HID + c] = mx;
    }
}

// q1base[b][j] = qb1[j] + tree_emb[b] @ qW1[:384]  (shared across 32 actions)
__global__ void k_qbase(const float* __restrict__ qW1, const float* __restrict__ qb1) {
    int b = blockIdx.x, j = threadIdx.x;
    const float* tr = g_tree + b * 3 * HID;
    float s = qb1[j];
    #pragma unroll 4
    for (int k = 0; k < 3 * HID; k++) s = fmaf(tr[k], qW1[k * HID + j], s);
    g_q1b[b * HID + j] = s;
}

// Fused action-MLP + Q-MLP: 8 actions per block (amortize weight reads).
#define ACT_PB 8
__global__ void __launch_bounds__(128)
k_act(const float* __restrict__ act, const int* __restrict__ bptr,
      const float* __restrict__ aW1, const float* __restrict__ ab1,
      const float* __restrict__ aW2, const float* __restrict__ ab2,
      const float* __restrict__ qW1,
      const float* __restrict__ qW2, const float* __restrict__ qb2,
      const float* __restrict__ qW3, const float* __restrict__ qb3,
      float* __restrict__ out) {
    const int AI = NIDX * HID + (ADIM - NIDX);   // 515
    int b  = blockIdx.x / (NA / ACT_PB);
    int a0 = (blockIdx.x % (NA / ACT_PB)) * ACT_PB;
    int t = threadIdx.x;

    __shared__ float ai[ACT_PB][NIDX * HID + (ADIM - NIDX)];
    __shared__ float v1[ACT_PB][HID];
    __shared__ float v2[ACT_PB][HID];

    int base = bptr[b];
    #pragma unroll
    for (int a = 0; a < ACT_PB; a++) {
        const float* arow = act + (size_t)(b * NA + a0 + a) * ADIM;
        #pragma unroll
        for (int i = 0; i < NIDX; i++) {
            int nidx = (int)arow[i] + base;
            ai[a][i * HID + t] = g_h[(size_t)nidx * HID + t];
        }
        if (t < ADIM - NIDX) ai[a][NIDX * HID + t] = arow[NIDX + t];
    }
    __syncthreads();

    float acc[ACT_PB];

    // a1: relu(ai @ aW1 + ab1)
    {
        float bv = ab1[t];
        #pragma unroll
        for (int a = 0; a < ACT_PB; a++) acc[a] = bv;
        for (int k = 0; k < AI; k++) {
            float w = aW1[k * HID + t];
            #pragma unroll
            for (int a = 0; a < ACT_PB; a++) acc[a] = fmaf(ai[a][k], w, acc[a]);
        }
        #pragma unroll
        for (int a = 0; a < ACT_PB; a++) v1[a][t] = fmaxf(acc[a], 0.f);
    }
    __syncthreads();

    // a2: ae = relu(v1 @ aW2 + ab2)
    {
        float bv = ab2[t];
        #pragma unroll
        for (int a = 0; a < ACT_PB; a++) acc[a] = bv;
        #pragma unroll 4
        for (int k = 0; k < HID; k++) {
            float w = aW2[k * HID + t];
            #pragma unroll
            for (int a = 0; a < ACT_PB; a++) acc[a] = fmaf(v1[a][k], w, acc[a]);
        }
        #pragma unroll
        for (int a = 0; a < ACT_PB; a++) v2[a][t] = fmaxf(acc[a], 0.f);
    }
    __syncthreads();

    // q1: relu(q1base + ae @ qW1[384:])
    {
        float bv = g_q1b[b * HID + t];
        #pragma unroll
        for (int a = 0; a < ACT_PB; a++) acc[a] = bv;
        #pragma unroll 4
        for (int k = 0; k < HID; k++) {
            float w = qW1[(3 * HID + k) * HID + t];
            #pragma unroll
            for (int a = 0; a < ACT_PB; a++) acc[a] = fmaf(v2[a][k], w, acc[a]);
        }
        #pragma unroll
        for (int a = 0; a < ACT_PB; a++) v1[a][t] = fmaxf(acc[a], 0.f);
    }
    __syncthreads();

    // q2: relu(v1 @ qW2 + qb2)
    {
        float bv = qb2[t];
        #pragma unroll
        for (int a = 0; a < ACT_PB; a++) acc[a] = bv;
        #pragma unroll 4
        for (int k = 0; k < HID; k++) {
            float w = qW2[k * HID + t];
            #pragma unroll
            for (int a = 0; a < ACT_PB; a++) acc[a] = fmaf(v1[a][k], w, acc[a]);
        }
        #pragma unroll
        for (int a = 0; a < ACT_PB; a++) v2[a][t] = fmaxf(acc[a], 0.f);
    }
    __syncthreads();

    // q3: scalar head
    __shared__ float ws[4];
    float w3 = qW3[t];
    for (int a = 0; a < ACT_PB; a++) {
        float q = v2[a][t] * w3;
        #pragma unroll
        for (int o = 16; o; o >>= 1) q += __shfl_xor_sync(0xffffffffu, q, o);
        if ((t & 31) == 0) ws[t >> 5] = q;
        __syncthreads();
        if (t == 0) out[b * NA + a0 + a] = ws[0] + ws[1] + ws[2] + ws[3] + qb3[0];
        __syncthreads();
    }
}

// ---------------------------------------------------------------------------
extern "C" void kernel_launch(void* const* d_in, const int* in_sizes, int n_in,
                              void* d_out, int out_size) {
    const float *x, *edge_attr, *act, *Wn, *bn, *gWl, *gbl, *gWr, *gbr, *gWe, *gatt, *gb;
    const float *aW1, *ab1, *aW2, *ab2, *qW1, *qb1, *qW2, *qb2, *qW3, *qb3;
    const int *eidx, *bptr;

    if (in_sizes[3] == 2 * NEDGE) {
        // dict order
        x = (const float*)d_in[0];  edge_attr = (const float*)d_in[1];
        act = (const float*)d_in[2];
        eidx = (const int*)d_in[3]; bptr = (const int*)d_in[5];
        Wn = (const float*)d_in[6];  bn  = (const float*)d_in[7];
        gWl = (const float*)d_in[8]; gWr = (const float*)d_in[9];
        gWe = (const float*)d_in[10]; gatt = (const float*)d_in[11];
        gbl = (const float*)d_in[12]; gbr = (const float*)d_in[13];
        gb  = (const float*)d_in[14];
        aW1 = (const float*)d_in[15]; ab1 = (const float*)d_in[16];
        aW2 = (const float*)d_in[17]; ab2 = (const float*)d_in[18];
        qW1 = (const float*)d_in[19]; qb1 = (const float*)d_in[20];
        qW2 = (const float*)d_in[21]; qb2 = (const float*)d_in[22];
        qW3 = (const float*)d_in[23]; qb3 = (const float*)d_in[24];
    } else {
        // reference-signature order
        x = (const float*)d_in[0];  edge_attr = (const float*)d_in[1];
        act = (const float*)d_in[2];
        Wn = (const float*)d_in[3];  bn  = (const float*)d_in[4];
        gWl = (const float*)d_in[5]; gbl = (const float*)d_in[6];
        gWr = (const float*)d_in[7]; gbr = (const float*)d_in[8];
        gWe = (const float*)d_in[9]; gatt = (const float*)d_in[10];
        gb  = (const float*)d_in[11];
        aW1 = (const float*)d_in[12]; ab1 = (const float*)d_in[13];
        aW2 = (const float*)d_in[14]; ab2 = (const float*)d_in[15];
        qW1 = (const float*)d_in[16]; qb1 = (const float*)d_in[17];
        qW2 = (const float*)d_in[18]; qb2 = (const float*)d_in[19];
        qW3 = (const float*)d_in[20]; qb3 = (const float*)d_in[21];
        eidx = (const int*)d_in[22]; bptr = (const int*)d_in[24];
    }
    float* out = (float*)d_out;
    const int* esrc = eidx;
    const int* edst = eidx + NEDGE;

    // Graph structure (rebuilt every launch: deterministic, input-dependent)
    k_init   <<<NNODES / 256, 256>>>();
    k_easum  <<<NEDGE / 256, 256>>>(edge_attr);
    k_deg    <<<NEDGE / 256, 256>>>(edst);
    k_scan1  <<<256, 256>>>();
    k_scan2  <<<1, 256>>>();
    k_scan3  <<<256, 256>>>();
    k_scatter<<<(NTOT + 255) / 256, 256>>>(edst);

    // Node encoder
    k_h0<<<(NNODES * HID) / 256, 256>>>(x, Wn, bn);

    // GATv2 layers
    for (int l = 0; l < NLAY; l++) {
        k_gemm2<<<NNODES / GR, 256>>>(gWl + l * HID * HID, gbl + l * HID,
                                      gWr + l * HID * HID, gbr + l * HID);
        k_gat<<<NNODES, 128>>>(esrc, edge_attr,
                               gWe + l * HID, gatt + l * NHEAD * CDIM, gb + l * HID);
    }

    // Readout + heads
    k_pool <<<NB, 1024>>>();
    k_qbase<<<NB, HID>>>(qW1, qb1);
    k_act  <<<NB * (NA / ACT_PB), HID>>>(act, bptr, aW1, ab1, aW2, ab2,
                                         qW1, qW2, qb2, qW3, qb3, out);
}